// round 1
// baseline (speedup 1.0000x reference)
#include <cuda_runtime.h>
#include <math.h>

#define BB 4
#define NN 2000
#define CCLS 80
#define KTOP 2000
#define CAP 8192
#define SCORE_THR 0.05f
#define IOU_THR 0.5f
#define MAXR 4.135166556742356f   /* |log(16/1000)| */

// ---------------- device scratch (no allocations allowed) ----------------
__device__ unsigned long long g_keys[BB][CAP];
__device__ int g_count[BB];
__device__ float g_box[BB][KTOP][4];
__device__ float g_score[BB][KTOP];
__device__ int g_label[BB][KTOP];
__device__ unsigned short g_cls_list[BB][CCLS][KTOP];
__device__ int g_cls_cnt[BB][CCLS];
__device__ unsigned char g_keep[BB][KTOP];

// ---------------- 0) reset per-replay state ----------------
__global__ void k_init() {
    int i = blockIdx.x * blockDim.x + threadIdx.x;
    if (i < BB * CAP) ((unsigned long long*)g_keys)[i] = 0ull;
    if (i < BB) g_count[i] = 0;
    if (i < BB * CCLS) ((int*)g_cls_cnt)[i] = 0;
}

// ---------------- 1) softmax + threshold + compact ----------------
// one warp per proposal: 81 logits -> 80 fg scores; push key if > thr
__global__ void k_score(const float* __restrict__ cls) {
    int warp = (blockIdx.x * blockDim.x + threadIdx.x) >> 5;
    int lane = threadIdx.x & 31;
    if (warp >= BB * NN) return;
    int b = warp / NN, n = warp % NN;
    const float* p = cls + ((size_t)b * NN + n) * (CCLS + 1);

    float x0 = p[lane];
    float x1 = p[lane + 32];
    float x2 = (lane < 17) ? p[lane + 64] : -1e30f;   // index 80 = background (lane16's x2)
    float m = fmaxf(x0, fmaxf(x1, x2));
    #pragma unroll
    for (int o = 16; o > 0; o >>= 1) m = fmaxf(m, __shfl_xor_sync(0xffffffffu, m, o));
    float e0 = expf(x0 - m);
    float e1 = expf(x1 - m);
    float e2 = (lane < 17) ? expf(x2 - m) : 0.f;
    float s = e0 + e1 + e2;
    #pragma unroll
    for (int o = 16; o > 0; o >>= 1) s += __shfl_xor_sync(0xffffffffu, s, o);

    // foreground classes only (0..79); key = score_bits<<32 | ~flat_idx
    // (positive float bits are order-monotonic; ~idx -> lower idx wins ties, matching lax.top_k)
    float sc;
    sc = e0 / s;
    if (sc > SCORE_THR) {
        unsigned idx = (unsigned)(n * CCLS + lane);
        unsigned long long key = ((unsigned long long)__float_as_uint(sc) << 32) | (0xFFFFFFFFu - idx);
        int pos = atomicAdd(&g_count[b], 1);
        if (pos < CAP) g_keys[b][pos] = key;
    }
    sc = e1 / s;
    if (sc > SCORE_THR) {
        unsigned idx = (unsigned)(n * CCLS + lane + 32);
        unsigned long long key = ((unsigned long long)__float_as_uint(sc) << 32) | (0xFFFFFFFFu - idx);
        int pos = atomicAdd(&g_count[b], 1);
        if (pos < CAP) g_keys[b][pos] = key;
    }
    if (lane < 16) {                                   // classes 64..79 (80 is bg)
        sc = e2 / s;
        if (sc > SCORE_THR) {
            unsigned idx = (unsigned)(n * CCLS + lane + 64);
            unsigned long long key = ((unsigned long long)__float_as_uint(sc) << 32) | (0xFFFFFFFFu - idx);
            int pos = atomicAdd(&g_count[b], 1);
            if (pos < CAP) g_keys[b][pos] = key;
        }
    }
}

// ---------------- 2) bitonic sort (descending) of CAP keys in smem ----------------
__global__ void k_sort() {
    extern __shared__ unsigned long long sk[];
    int b = blockIdx.x;
    int tid = threadIdx.x;
    for (int i = tid; i < CAP; i += blockDim.x) sk[i] = g_keys[b][i];
    __syncthreads();
    for (int k = 2; k <= CAP; k <<= 1) {
        for (int j = k >> 1; j > 0; j >>= 1) {
            for (int t = tid; t < CAP; t += blockDim.x) {
                int ixj = t ^ j;
                if (ixj > t) {
                    unsigned long long a = sk[t], c = sk[ixj];
                    bool descBlock = ((t & k) == 0);
                    if (descBlock ? (a < c) : (a > c)) { sk[t] = c; sk[ixj] = a; }
                }
            }
            __syncthreads();
        }
    }
    for (int i = tid; i < KTOP; i += blockDim.x) g_keys[b][i] = sk[i];
}

// ---------------- 3) decode the top-2000 boxes only ----------------
__global__ void k_decode(const float* __restrict__ reg, const float* __restrict__ props,
                         const int* __restrict__ hw) {
    int g = blockIdx.x * blockDim.x + threadIdx.x;
    if (g >= BB * KTOP) return;
    int b = g / KTOP, s = g % KTOP;
    g_keep[b][s] = 0;
    int cnt = min(g_count[b], CAP);
    unsigned long long key = g_keys[b][s];
    if (s >= cnt || key == 0ull) {
        g_score[b][s] = -1.f;
        g_label[b][s] = -1;
        g_box[b][s][0] = g_box[b][s][1] = g_box[b][s][2] = g_box[b][s][3] = 0.f;
        return;
    }
    float sc = __uint_as_float((unsigned)(key >> 32));
    unsigned idx = 0xFFFFFFFFu - (unsigned)(key & 0xFFFFFFFFu);
    int n = idx / CCLS, c = idx % CCLS;
    float h = (float)hw[b * 2 + 0], w = (float)hw[b * 2 + 1];
    const float* pb = props + ((size_t)b * NN + n) * 4;
    const float* d = reg + (((size_t)b * NN + n) * CCLS + c) * 4;
    float dx = d[0] * 0.1f, dy = d[1] * 0.1f;
    float dw = fminf(fmaxf(d[2] * 0.2f, -MAXR), MAXR);
    float dh = fminf(fmaxf(d[3] * 0.2f, -MAXR), MAXR);
    float px = (pb[0] + pb[2]) * 0.5f, py = (pb[1] + pb[3]) * 0.5f;
    float pw = pb[2] - pb[0], ph = pb[3] - pb[1];
    float gx = px + pw * dx, gy = py + ph * dy;
    float gw = pw * expf(dw), gh = ph * expf(dh);
    g_box[b][s][0] = fminf(fmaxf(gx - gw * 0.5f, 0.f), w);
    g_box[b][s][1] = fminf(fmaxf(gy - gh * 0.5f, 0.f), h);
    g_box[b][s][2] = fminf(fmaxf(gx + gw * 0.5f, 0.f), w);
    g_box[b][s][3] = fminf(fmaxf(gy + gh * 0.5f, 0.f), h);
    g_score[b][s] = sc;
    g_label[b][s] = c;
}

// ---------------- 4) stable per-class index lists (score order preserved) ----------------
__global__ void k_classlist() {
    __shared__ short slab[KTOP];
    __shared__ int scnt[CCLS];
    int b = blockIdx.x, tid = threadIdx.x;
    for (int i = tid; i < KTOP; i += blockDim.x) slab[i] = (short)g_label[b][i];
    if (tid < CCLS) scnt[tid] = 0;
    __syncthreads();
    for (int s = tid; s < KTOP; s += blockDim.x) {
        int lab = slab[s];
        if (lab >= 0) {
            int r = 0;
            for (int j = 0; j < s; j++) r += (slab[j] == lab);
            g_cls_list[b][lab][r] = (unsigned short)s;
            atomicAdd(&scnt[lab], 1);
        }
    }
    __syncthreads();
    if (tid < CCLS) g_cls_cnt[b][tid] = scnt[tid];
}

// ---------------- 5) per-class greedy NMS (one warp per (class,image)) ----------------
// class-offset trick: cross-class IoU is exactly 0, so NMS decomposes per class.
// offset still added (like reference) so rounding near the 0.5 threshold matches.
__global__ void k_nms(const int* __restrict__ hw) {
    __shared__ float bx[KTOP][4];     // 32 KB
    __shared__ float ar[KTOP];        //  8 KB
    __shared__ unsigned char sup[KTOP];
    int c = blockIdx.x, b = blockIdx.y;
    int lane = threadIdx.x;
    int k = g_cls_cnt[b][c];
    if (k == 0) return;
    float h = (float)hw[b * 2 + 0], w = (float)hw[b * 2 + 1];
    float off = (float)c * (fmaxf(h, w) + 1.0f);
    for (int t = lane; t < k; t += 32) {
        int it = g_cls_list[b][c][t];
        float x1 = g_box[b][it][0] + off;
        float y1 = g_box[b][it][1] + off;
        float x2 = g_box[b][it][2] + off;
        float y2 = g_box[b][it][3] + off;
        bx[t][0] = x1; bx[t][1] = y1; bx[t][2] = x2; bx[t][3] = y2;
        ar[t] = (x2 - x1) * (y2 - y1);
        sup[t] = 0;
    }
    __syncwarp();
    for (int a = 0; a < k - 1; a++) {
        if (!sup[a]) {
            float ax1 = bx[a][0], ay1 = bx[a][1], ax2 = bx[a][2], ay2 = bx[a][3], aa = ar[a];
            for (int t = a + 1 + lane; t < k; t += 32) {
                if (sup[t]) continue;
                float ix1 = fmaxf(ax1, bx[t][0]);
                float iy1 = fmaxf(ay1, bx[t][1]);
                float ix2 = fminf(ax2, bx[t][2]);
                float iy2 = fminf(ay2, bx[t][3]);
                float iw = fmaxf(ix2 - ix1, 0.f), ih = fmaxf(iy2 - iy1, 0.f);
                float inter = iw * ih;
                float iou = inter / (aa + ar[t] - inter + 1e-6f);
                if (iou > IOU_THR) sup[t] = 1;
            }
        }
        __syncwarp();
    }
    for (int t = lane; t < k; t += 32)
        if (!sup[t]) g_keep[b][g_cls_list[b][c][t]] = 1;
}

// ---------------- 6) rank kept items, write top-100 outputs ----------------
// out layout (float32): boxes [B,100,4] | scores [B,100] | labels [B,100]
__global__ void k_final(float* __restrict__ out) {
    __shared__ unsigned char skeep[KTOP];
    int b = blockIdx.x, tid = threadIdx.x;
    for (int i = tid; i < KTOP; i += blockDim.x) skeep[i] = g_keep[b][i];
    __syncthreads();
    float* ob = out;
    float* os = out + BB * 100 * 4;
    float* ol = out + BB * 100 * 5;
    for (int r = tid; r < 100; r += blockDim.x) {
        ob[(b * 100 + r) * 4 + 0] = 0.f;
        ob[(b * 100 + r) * 4 + 1] = 0.f;
        ob[(b * 100 + r) * 4 + 2] = 0.f;
        ob[(b * 100 + r) * 4 + 3] = 0.f;
        os[b * 100 + r] = 0.f;
        ol[b * 100 + r] = -1.f;
    }
    __syncthreads();
    for (int s = tid; s < KTOP; s += blockDim.x) {
        if (skeep[s]) {
            int r = 0;
            for (int j = 0; j < s; j++) r += skeep[j];
            if (r < 100) {
                ob[(b * 100 + r) * 4 + 0] = g_box[b][s][0];
                ob[(b * 100 + r) * 4 + 1] = g_box[b][s][1];
                ob[(b * 100 + r) * 4 + 2] = g_box[b][s][2];
                ob[(b * 100 + r) * 4 + 3] = g_box[b][s][3];
                os[b * 100 + r] = g_score[b][s];
                ol[b * 100 + r] = (float)g_label[b][s];
            }
        }
    }
}

// ---------------- launch ----------------
extern "C" void kernel_launch(void* const* d_in, const int* in_sizes, int n_in,
                              void* d_out, int out_size) {
    const float* cls   = (const float*)d_in[0];   // [B,N,81]
    const float* reg   = (const float*)d_in[1];   // [B,N,320]
    const float* props = (const float*)d_in[2];   // [B,N,4]
    const int*   hw    = (const int*)d_in[3];     // [B,2]
    float* out = (float*)d_out;

    cudaFuncSetAttribute(k_sort, cudaFuncAttributeMaxDynamicSharedMemorySize, CAP * 8);

    k_init<<<(BB * CAP + 255) / 256, 256>>>();
    k_score<<<(BB * NN * 32 + 255) / 256, 256>>>(cls);
    k_sort<<<BB, 1024, CAP * 8>>>();
    k_decode<<<(BB * KTOP + 255) / 256, 256>>>(reg, props, hw);
    k_classlist<<<BB, 1024>>>();
    k_nms<<<dim3(CCLS, BB), 32>>>(hw);
    k_final<<<BB, 1024>>>(out);
}

// round 3
// speedup vs baseline: 2.1247x; 2.1247x over previous
#include <cuda_runtime.h>
#include <math.h>

#define BB 4
#define NN 2000
#define CCLS 80
#define KTOP 2000
#define CAP 8192
#define CMAX 160
#define SCORE_THR 0.05f
#define IOU_THR 0.5f
#define MAXR 4.135166556742356f   /* |log(16/1000)| */

// ---------------- device scratch ----------------
__device__ unsigned long long g_keys[BB][CAP];
__device__ int g_count[BB];
__device__ float4 g_boxv[BB][KTOP];
__device__ float g_scorev[BB][KTOP];
__device__ unsigned char g_lab[BB][KTOP];

// ---------------- 0) reset per-replay state ----------------
__global__ void k_init() {
    int i = blockIdx.x * blockDim.x + threadIdx.x;
    if (i < BB * CAP) ((unsigned long long*)g_keys)[i] = 0ull;
    if (i < BB) g_count[i] = 0;
}

// ---------------- 1) softmax + threshold + compact (block-aggregated) ----------------
// one warp per proposal, 8 warps per block (all same image since 2000 % 8 == 0)
__global__ void k_score(const float* __restrict__ cls) {
    __shared__ unsigned long long buf[640];
    __shared__ int bcnt;
    __shared__ int gbase;
    int wib = threadIdx.x >> 5;
    int lane = threadIdx.x & 31;
    int warp = blockIdx.x * 8 + wib;
    int b = warp / NN, n = warp % NN;
    if (threadIdx.x == 0) bcnt = 0;
    __syncthreads();

    const float* p = cls + ((size_t)b * NN + n) * (CCLS + 1);
    float x0 = p[lane];
    float x1 = p[lane + 32];
    float x2 = (lane < 17) ? p[lane + 64] : -1e30f;   // idx 80 = background
    float m = fmaxf(x0, fmaxf(x1, x2));
    #pragma unroll
    for (int o = 16; o > 0; o >>= 1) m = fmaxf(m, __shfl_xor_sync(0xffffffffu, m, o));
    float e0 = expf(x0 - m);
    float e1 = expf(x1 - m);
    float e2 = (lane < 17) ? expf(x2 - m) : 0.f;
    float s = e0 + e1 + e2;
    #pragma unroll
    for (int o = 16; o > 0; o >>= 1) s += __shfl_xor_sync(0xffffffffu, s, o);

    float sc;
    sc = e0 / s;
    if (sc > SCORE_THR) {
        unsigned idx = (unsigned)(n * CCLS + lane);
        buf[atomicAdd(&bcnt, 1)] = ((unsigned long long)__float_as_uint(sc) << 32) | (0xFFFFFFFFu - idx);
    }
    sc = e1 / s;
    if (sc > SCORE_THR) {
        unsigned idx = (unsigned)(n * CCLS + lane + 32);
        buf[atomicAdd(&bcnt, 1)] = ((unsigned long long)__float_as_uint(sc) << 32) | (0xFFFFFFFFu - idx);
    }
    if (lane < 16) {
        sc = e2 / s;
        if (sc > SCORE_THR) {
            unsigned idx = (unsigned)(n * CCLS + lane + 64);
            buf[atomicAdd(&bcnt, 1)] = ((unsigned long long)__float_as_uint(sc) << 32) | (0xFFFFFFFFu - idx);
        }
    }
    __syncthreads();
    if (threadIdx.x == 0) gbase = atomicAdd(&g_count[b], bcnt);
    __syncthreads();
    int nb = bcnt, gb = gbase;
    for (int i = threadIdx.x; i < nb; i += blockDim.x) {
        int pos = gb + i;
        if (pos < CAP) g_keys[b][pos] = buf[i];
    }
}

// ---------------- 2a) local bitonic sort of 2048-chunks (16 blocks) ----------------
// chunk even -> descending, chunk odd -> ascending
__global__ void k_sort1() {
    __shared__ unsigned long long sk[2048];
    int b = blockIdx.x >> 2, chunk = blockIdx.x & 3;
    int tid = threadIdx.x;
    unsigned long long* src = &g_keys[b][chunk * 2048];
    for (int i = tid; i < 2048; i += 1024) sk[i] = src[i];
    __syncthreads();
    bool flip = (chunk & 1);
    for (int k = 2; k <= 2048; k <<= 1) {
        for (int j = k >> 1; j > 0; j >>= 1) {
            for (int t = tid; t < 2048; t += 1024) {
                int ixj = t ^ j;
                if (ixj > t) {
                    unsigned long long a = sk[t], c = sk[ixj];
                    bool desc = (((t & k) == 0) != flip);
                    if (desc ? (a < c) : (a > c)) { sk[t] = c; sk[ixj] = a; }
                }
            }
            __syncthreads();
        }
    }
    for (int i = tid; i < 2048; i += 1024) src[i] = sk[i];
}

// ---------------- 2b) merge 4096 windows (8 blocks); win0 desc, win1 asc ----------------
__global__ void k_sort2() {
    __shared__ unsigned long long sk[4096];
    int b = blockIdx.x >> 1, win = blockIdx.x & 1;
    int tid = threadIdx.x;
    unsigned long long* src = &g_keys[b][win * 4096];
    for (int i = tid; i < 4096; i += 1024) sk[i] = src[i];
    __syncthreads();
    bool desc = (win == 0);
    for (int j = 2048; j > 0; j >>= 1) {
        for (int t = tid; t < 4096; t += 1024) {
            int ixj = t ^ j;
            if (ixj > t) {
                unsigned long long a = sk[t], c = sk[ixj];
                if (desc ? (a < c) : (a > c)) { sk[t] = c; sk[ixj] = a; }
            }
        }
        __syncthreads();
    }
    for (int i = tid; i < 4096; i += 1024) src[i] = sk[i];
}

// ---------------- 2c) final 8192 merge (desc) + fused decode of top-2000 ----------------
__global__ void k_sort3(const float* __restrict__ reg, const float* __restrict__ props,
                        const int* __restrict__ hw) {
    extern __shared__ unsigned long long sk[];
    int b = blockIdx.x, tid = threadIdx.x;
    for (int i = tid; i < CAP; i += 1024) sk[i] = g_keys[b][i];
    __syncthreads();
    for (int j = 4096; j > 0; j >>= 1) {
        for (int t = tid; t < CAP; t += 1024) {
            int ixj = t ^ j;
            if (ixj > t) {
                unsigned long long a = sk[t], c = sk[ixj];
                if (a < c) { sk[t] = c; sk[ixj] = a; }
            }
        }
        __syncthreads();
    }
    // decode top-2000
    int cnt = min(g_count[b], CAP);
    float h = (float)hw[b * 2 + 0], w = (float)hw[b * 2 + 1];
    for (int s = tid; s < KTOP; s += 1024) {
        unsigned long long key = sk[s];
        if (s >= cnt || key == 0ull) {
            g_scorev[b][s] = 0.f;
            g_lab[b][s] = 255;
            g_boxv[b][s] = make_float4(0.f, 0.f, 0.f, 0.f);
            continue;
        }
        float sc = __uint_as_float((unsigned)(key >> 32));
        unsigned idx = 0xFFFFFFFFu - (unsigned)(key & 0xFFFFFFFFu);
        int n = idx / CCLS, c = idx % CCLS;
        const float* pb = props + ((size_t)b * NN + n) * 4;
        const float* d = reg + (((size_t)b * NN + n) * CCLS + c) * 4;
        float dx = d[0] * 0.1f, dy = d[1] * 0.1f;
        float dw = fminf(fmaxf(d[2] * 0.2f, -MAXR), MAXR);
        float dh = fminf(fmaxf(d[3] * 0.2f, -MAXR), MAXR);
        float px = (pb[0] + pb[2]) * 0.5f, py = (pb[1] + pb[3]) * 0.5f;
        float pw = pb[2] - pb[0], ph = pb[3] - pb[1];
        float gx = px + pw * dx, gy = py + ph * dy;
        float gw = pw * expf(dw), gh = ph * expf(dh);
        g_boxv[b][s] = make_float4(
            fminf(fmaxf(gx - gw * 0.5f, 0.f), w),
            fminf(fmaxf(gy - gh * 0.5f, 0.f), h),
            fminf(fmaxf(gx + gw * 0.5f, 0.f), w),
            fminf(fmaxf(gy + gh * 0.5f, 0.f), h));
        g_scorev[b][s] = sc;
        g_lab[b][s] = (unsigned char)c;
    }
}

// ---------------- 3) classlist + per-class NMS + rank + output (1 block/image) ----------------
// smem carve: sbox 32000 | sar 8000 | ssc 8000 | slist 25600 | scnt 320 | wtot 128 | slab 2000 | ssup 2000
#define PM_SBOX  0
#define PM_SAR   32000
#define PM_SSC   40000
#define PM_LIST  48000
#define PM_CNT   73600
#define PM_WTOT  73920
#define PM_LAB   74048
#define PM_SUP   76048
#define PM_TOTAL 78080

__global__ void k_post(const int* __restrict__ hw, float* __restrict__ out) {
    extern __shared__ unsigned char pmem[];
    float4* sbox = (float4*)(pmem + PM_SBOX);
    float* sar = (float*)(pmem + PM_SAR);
    float* ssc = (float*)(pmem + PM_SSC);
    unsigned short* slist = (unsigned short*)(pmem + PM_LIST);
    int* scnt = (int*)(pmem + PM_CNT);
    int* wtot = (int*)(pmem + PM_WTOT);
    unsigned char* slab = pmem + PM_LAB;
    unsigned char* ssup = pmem + PM_SUP;

    int b = blockIdx.x, tid = threadIdx.x;
    int wid = tid >> 5, lane = tid & 31;
    float h = (float)hw[b * 2 + 0], w = (float)hw[b * 2 + 1];
    float offs = fmaxf(h, w) + 1.0f;

    // default outputs
    float* ob = out;
    float* os = out + BB * 100 * 4;
    float* ol = out + BB * 100 * 5;
    for (int r = tid; r < 100; r += 1024) {
        ob[(b * 100 + r) * 4 + 0] = 0.f;
        ob[(b * 100 + r) * 4 + 1] = 0.f;
        ob[(b * 100 + r) * 4 + 2] = 0.f;
        ob[(b * 100 + r) * 4 + 3] = 0.f;
        os[b * 100 + r] = 0.f;
        ol[b * 100 + r] = -1.f;
    }

    // load + apply class offset (matches reference fp rounding)
    for (int s = tid; s < KTOP; s += 1024) {
        unsigned char l = g_lab[b][s];
        slab[s] = l;
        ssup[s] = 0;
        ssc[s] = g_scorev[b][s];
        float4 bx = g_boxv[b][s];
        float off = (l != 255) ? (float)l * offs : 0.f;
        bx.x += off; bx.y += off; bx.z += off; bx.w += off;
        sbox[s] = bx;
        sar[s] = (bx.z - bx.x) * (bx.w - bx.y);
    }
    __syncthreads();

    // stable per-class lists via warp ballot compaction
    for (int c = wid; c < CCLS; c += 32) {
        int cnt = 0;
        for (int base = 0; base < KTOP; base += 32) {
            int s = base + lane;
            int l = (s < KTOP) ? (int)slab[s] : 255;
            unsigned mask = __ballot_sync(0xffffffffu, l == c);
            if (l == c) {
                int r = cnt + __popc(mask & ((1u << lane) - 1u));
                if (r < CMAX) slist[c * CMAX + r] = (unsigned short)s;
            }
            cnt += __popc(mask);
        }
        if (lane == 0) scnt[c] = min(cnt, CMAX);
    }
    __syncthreads();

    // greedy NMS per class (cross-class IoU is exactly 0 via the offset trick)
    for (int c = wid; c < CCLS; c += 32) {
        int k = scnt[c];
        for (int a = 0; a < k - 1; a++) {
            int ia = slist[c * CMAX + a];
            if (!ssup[ia]) {
                float4 A = sbox[ia];
                float aa = sar[ia];
                for (int t = a + 1 + lane; t < k; t += 32) {
                    int it = slist[c * CMAX + t];
                    if (ssup[it]) continue;
                    float4 Bx = sbox[it];
                    float ix1 = fmaxf(A.x, Bx.x);
                    float iy1 = fmaxf(A.y, Bx.y);
                    float ix2 = fminf(A.z, Bx.z);
                    float iy2 = fminf(A.w, Bx.w);
                    float iw = fmaxf(ix2 - ix1, 0.f), ih = fmaxf(iy2 - iy1, 0.f);
                    float inter = iw * ih;
                    float iou = inter / (aa + sar[it] - inter + 1e-6f);
                    if (iou > IOU_THR) ssup[it] = 1;
                }
            }
            __syncwarp();
        }
    }
    __syncthreads();

    // hierarchical block scan of keep flags -> ranks; write top-100
    int s0 = 2 * tid, s1 = 2 * tid + 1;
    int f0 = (s0 < KTOP) && (slab[s0] != 255) && !ssup[s0];
    int f1 = (s1 < KTOP) && (slab[s1] != 255) && !ssup[s1];
    int loc = f0 + f1;
    int incl = loc;
    #pragma unroll
    for (int o = 1; o < 32; o <<= 1) {
        int v = __shfl_up_sync(0xffffffffu, incl, o);
        if (lane >= o) incl += v;
    }
    if (lane == 31) wtot[wid] = incl;
    __syncthreads();
    if (wid == 0) {
        int v = wtot[lane];
        int inc2 = v;
        #pragma unroll
        for (int o = 1; o < 32; o <<= 1) {
            int u = __shfl_up_sync(0xffffffffu, inc2, o);
            if (lane >= o) inc2 += u;
        }
        wtot[lane] = inc2 - v;  // exclusive warp base
    }
    __syncthreads();
    int base = wtot[wid] + incl - loc;
    if (f0 && base < 100) {
        int r = base;
        float off = (float)slab[s0] * offs;
        float4 bx = sbox[s0];
        ob[(b * 100 + r) * 4 + 0] = bx.x - off;
        ob[(b * 100 + r) * 4 + 1] = bx.y - off;
        ob[(b * 100 + r) * 4 + 2] = bx.z - off;
        ob[(b * 100 + r) * 4 + 3] = bx.w - off;
        os[b * 100 + r] = ssc[s0];
        ol[b * 100 + r] = (float)slab[s0];
    }
    if (f1 && base + f0 < 100) {
        int r = base + f0;
        float off = (float)slab[s1] * offs;
        float4 bx = sbox[s1];
        ob[(b * 100 + r) * 4 + 0] = bx.x - off;
        ob[(b * 100 + r) * 4 + 1] = bx.y - off;
        ob[(b * 100 + r) * 4 + 2] = bx.z - off;
        ob[(b * 100 + r) * 4 + 3] = bx.w - off;
        os[b * 100 + r] = ssc[s1];
        ol[b * 100 + r] = (float)slab[s1];
    }
}

// ---------------- launch ----------------
extern "C" void kernel_launch(void* const* d_in, const int* in_sizes, int n_in,
                              void* d_out, int out_size) {
    const float* cls   = (const float*)d_in[0];   // [B,N,81]
    const float* reg   = (const float*)d_in[1];   // [B,N,320]
    const float* props = (const float*)d_in[2];   // [B,N,4]
    const int*   hw    = (const int*)d_in[3];     // [B,2]
    float* out = (float*)d_out;

    cudaFuncSetAttribute(k_sort3, cudaFuncAttributeMaxDynamicSharedMemorySize, CAP * 8);
    cudaFuncSetAttribute(k_post, cudaFuncAttributeMaxDynamicSharedMemorySize, PM_TOTAL);

    k_init<<<(BB * CAP + 255) / 256, 256>>>();
    k_score<<<BB * NN / 8, 256>>>(cls);
    k_sort1<<<BB * 4, 1024>>>();
    k_sort2<<<BB * 2, 1024>>>();
    k_sort3<<<BB, 1024, CAP * 8>>>(reg, props, hw);
    k_post<<<BB, 1024, PM_TOTAL>>>(hw, out);
}

// round 4
// speedup vs baseline: 3.1552x; 1.4850x over previous
#include <cuda_runtime.h>
#include <math.h>

#define BB 4
#define NN 2000
#define CCLS 80
#define KTOP 2000
#define CAP 8192
#define CMAX 160
#define SCORE_THR 0.05f
#define IOU_THR 0.5f
#define MAXR 4.135166556742356f   /* |log(16/1000)| */

// bucket sort params: bucket = (score_bits >> 13) - BUCKET_BASE
#define NB 5120                    /* 5 buckets per thread @ 1024 threads */
#define SCAP 4096                  /* sorted-array capacity (need top 2000) */
#define BUCKET_BASE 125542u        /* 0x3D4CCCCD >> 13  (0.05f) */

// ---------------- device scratch ----------------
__device__ unsigned long long g_keys[BB][CAP];
__device__ int g_count[BB];        // zero-init at load; reset by k_mega each call

// ---------------- 1) softmax + threshold + compact (block-aggregated) ----------------
// one warp per proposal, 8 warps per block (blocks never straddle images: 2000%8==0)
__global__ void k_score(const float* __restrict__ cls) {
    __shared__ unsigned long long buf[640];
    __shared__ int bcnt;
    __shared__ int gbase;
    int wib = threadIdx.x >> 5;
    int lane = threadIdx.x & 31;
    int warp = blockIdx.x * 8 + wib;
    int b = warp / NN, n = warp % NN;
    if (threadIdx.x == 0) bcnt = 0;
    __syncthreads();

    const float* p = cls + ((size_t)b * NN + n) * (CCLS + 1);
    float x0 = p[lane];
    float x1 = p[lane + 32];
    float x2 = (lane < 17) ? p[lane + 64] : -1e30f;   // idx 80 = background
    float m = fmaxf(x0, fmaxf(x1, x2));
    #pragma unroll
    for (int o = 16; o > 0; o >>= 1) m = fmaxf(m, __shfl_xor_sync(0xffffffffu, m, o));
    float e0 = expf(x0 - m);
    float e1 = expf(x1 - m);
    float e2 = (lane < 17) ? expf(x2 - m) : 0.f;
    float s = e0 + e1 + e2;
    #pragma unroll
    for (int o = 16; o > 0; o >>= 1) s += __shfl_xor_sync(0xffffffffu, s, o);

    float sc;
    sc = e0 / s;
    if (sc > SCORE_THR) {
        unsigned idx = (unsigned)(n * CCLS + lane);
        buf[atomicAdd(&bcnt, 1)] = ((unsigned long long)__float_as_uint(sc) << 32) | (0xFFFFFFFFu - idx);
    }
    sc = e1 / s;
    if (sc > SCORE_THR) {
        unsigned idx = (unsigned)(n * CCLS + lane + 32);
        buf[atomicAdd(&bcnt, 1)] = ((unsigned long long)__float_as_uint(sc) << 32) | (0xFFFFFFFFu - idx);
    }
    if (lane < 16) {
        sc = e2 / s;
        if (sc > SCORE_THR) {
            unsigned idx = (unsigned)(n * CCLS + lane + 64);
            buf[atomicAdd(&bcnt, 1)] = ((unsigned long long)__float_as_uint(sc) << 32) | (0xFFFFFFFFu - idx);
        }
    }
    __syncthreads();
    if (threadIdx.x == 0) gbase = atomicAdd(&g_count[b], bcnt);
    __syncthreads();
    int nb = bcnt, gb = gbase;
    for (int i = threadIdx.x; i < nb; i += blockDim.x) {
        int pos = gb + i;
        if (pos < CAP) g_keys[b][pos] = buf[i];
    }
}

// ---------------- 2) mega: bucket-sort + decode + classlist + NMS + output ----------------
// smem carve (bytes):
#define PM_HIST  0                 /* int[5120]            20480 */
#define PM_SORT  20480             /* u64[4096]            32768 */
#define PM_SBOX  53248             /* float4[2000]         32000 */
#define PM_SAR   85248             /* float[2000]           8000 */
#define PM_SSC   93248             /* float[2000]           8000 */
#define PM_LIST  101248            /* ushort[80*160]       25600 */
#define PM_CNT   126848            /* int[80]                320 */
#define PM_WTOT  127168            /* int[32]                128 */
#define PM_LAB   127296            /* u8[2000]              2000 */
#define PM_SUP   129296            /* u8[2000]              2000 */
#define PM_TOTAL 131296

__global__ void k_mega(const float* __restrict__ reg, const float* __restrict__ props,
                       const int* __restrict__ hw, float* __restrict__ out) {
    extern __shared__ unsigned char pmem[];
    int* hist = (int*)(pmem + PM_HIST);
    unsigned long long* ssort = (unsigned long long*)(pmem + PM_SORT);
    float4* sbox = (float4*)(pmem + PM_SBOX);
    float* sar = (float*)(pmem + PM_SAR);
    float* ssc = (float*)(pmem + PM_SSC);
    unsigned short* slist = (unsigned short*)(pmem + PM_LIST);
    int* scnt = (int*)(pmem + PM_CNT);
    int* wtot = (int*)(pmem + PM_WTOT);
    unsigned char* slab = pmem + PM_LAB;
    unsigned char* ssup = pmem + PM_SUP;

    int b = blockIdx.x, tid = threadIdx.x;
    int wid = tid >> 5, lane = tid & 31;
    int cnt = min(g_count[b], CAP);
    float h = (float)hw[b * 2 + 0], w = (float)hw[b * 2 + 1];
    float offs = fmaxf(h, w) + 1.0f;

    // ---- phase 1: zero hist + ssort ----
    for (int i = tid; i < NB; i += 1024) hist[i] = 0;
    for (int i = tid; i < SCAP; i += 1024) ssort[i] = 0ull;
    __syncthreads();

    // ---- phase 2: histogram over score bits ----
    for (int i = tid; i < cnt; i += 1024) {
        unsigned u = (unsigned)(g_keys[b][i] >> 32);
        int bkt = min(max((int)((u >> 13) - BUCKET_BASE), 0), NB - 1);
        atomicAdd(&hist[bkt], 1);
    }
    __syncthreads();

    // ---- phase 3: suffix exclusive scan (start[bkt] = #items in higher buckets) ----
    // thread t owns reversed run [t*5, t*5+5): buckets NB-1-(t*5+k)
    int lc[5];
    int lsum = 0;
    #pragma unroll
    for (int k = 0; k < 5; k++) {
        lc[k] = hist[NB - 1 - (tid * 5 + k)];
        lsum += lc[k];
    }
    // block exclusive scan of lsum
    int incl = lsum;
    #pragma unroll
    for (int o = 1; o < 32; o <<= 1) {
        int v = __shfl_up_sync(0xffffffffu, incl, o);
        if (lane >= o) incl += v;
    }
    if (lane == 31) wtot[wid] = incl;
    __syncthreads();
    if (wid == 0) {
        int v = wtot[lane];
        int i2 = v;
        #pragma unroll
        for (int o = 1; o < 32; o <<= 1) {
            int u2 = __shfl_up_sync(0xffffffffu, i2, o);
            if (lane >= o) i2 += u2;
        }
        wtot[lane] = i2 - v;
    }
    __syncthreads();
    int run = wtot[wid] + incl - lsum;
    #pragma unroll
    for (int k = 0; k < 5; k++) {
        int bkt = NB - 1 - (tid * 5 + k);
        int c = lc[k];
        hist[bkt] = run;   // start cursor (each bucket owned by exactly one thread)
        run += c;
    }
    __syncthreads();

    // ---- phase 4: scatter ----
    for (int i = tid; i < cnt; i += 1024) {
        unsigned long long key = g_keys[b][i];
        unsigned u = (unsigned)(key >> 32);
        int bkt = min(max((int)((u >> 13) - BUCKET_BASE), 0), NB - 1);
        int pos = atomicAdd(&hist[bkt], 1);
        if (pos < SCAP) ssort[pos] = key;
    }
    __syncthreads();

    // ---- phase 5: per-bucket fix-up (insertion sort desc by full key) ----
    // post-scatter hist[bkt] = segment end; start = hist[bkt+1] (or 0 for top bucket)
    for (int bkt = tid; bkt < NB; bkt += 1024) {
        int e0 = hist[bkt];
        int s0 = (bkt == NB - 1) ? 0 : hist[bkt + 1];
        if (s0 >= KTOP) continue;                 // order beyond top-2000 irrelevant
        if (e0 > SCAP) e0 = SCAP;
        for (int i = s0 + 1; i < e0; i++) {
            unsigned long long v = ssort[i];
            int j = i - 1;
            while (j >= s0 && ssort[j] < v) { ssort[j + 1] = ssort[j]; j--; }
            ssort[j + 1] = v;
        }
    }
    __syncthreads();

    // ---- phase 6: decode top-2000 (+ class offset for NMS, matches ref rounding) ----
    for (int s = tid; s < KTOP; s += 1024) {
        unsigned long long key = ssort[s];
        if (s >= cnt || key == 0ull) {
            ssc[s] = 0.f;
            slab[s] = 255;
            ssup[s] = 0;
            sbox[s] = make_float4(0.f, 0.f, 0.f, 0.f);
            sar[s] = 0.f;
            continue;
        }
        float sc = __uint_as_float((unsigned)(key >> 32));
        unsigned idx = 0xFFFFFFFFu - (unsigned)(key & 0xFFFFFFFFu);
        int n = idx / CCLS, c = idx % CCLS;
        const float* pb = props + ((size_t)b * NN + n) * 4;
        const float* d = reg + (((size_t)b * NN + n) * CCLS + c) * 4;
        float dx = d[0] * 0.1f, dy = d[1] * 0.1f;
        float dw = fminf(fmaxf(d[2] * 0.2f, -MAXR), MAXR);
        float dh = fminf(fmaxf(d[3] * 0.2f, -MAXR), MAXR);
        float px = (pb[0] + pb[2]) * 0.5f, py = (pb[1] + pb[3]) * 0.5f;
        float pw = pb[2] - pb[0], ph = pb[3] - pb[1];
        float gx = px + pw * dx, gy = py + ph * dy;
        float gw = pw * expf(dw), gh = ph * expf(dh);
        float off = (float)c * offs;
        float x1 = fminf(fmaxf(gx - gw * 0.5f, 0.f), w) + off;
        float y1 = fminf(fmaxf(gy - gh * 0.5f, 0.f), h) + off;
        float x2 = fminf(fmaxf(gx + gw * 0.5f, 0.f), w) + off;
        float y2 = fminf(fmaxf(gy + gh * 0.5f, 0.f), h) + off;
        sbox[s] = make_float4(x1, y1, x2, y2);
        sar[s] = (x2 - x1) * (y2 - y1);
        ssc[s] = sc;
        slab[s] = (unsigned char)c;
        ssup[s] = 0;
    }
    __syncthreads();

    // ---- phase 7: stable per-class lists via warp ballot compaction ----
    for (int c = wid; c < CCLS; c += 32) {
        int cc = 0;
        for (int base = 0; base < KTOP; base += 32) {
            int s = base + lane;
            int l = (s < KTOP) ? (int)slab[s] : 255;
            unsigned mask = __ballot_sync(0xffffffffu, l == c);
            if (l == c) {
                int r = cc + __popc(mask & ((1u << lane) - 1u));
                if (r < CMAX) slist[c * CMAX + r] = (unsigned short)s;
            }
            cc += __popc(mask);
        }
        if (lane == 0) scnt[c] = min(cc, CMAX);
    }
    __syncthreads();

    // ---- phase 8: greedy NMS per class (cross-class IoU exactly 0 via offset) ----
    for (int c = wid; c < CCLS; c += 32) {
        int k = scnt[c];
        for (int a = 0; a < k - 1; a++) {
            int ia = slist[c * CMAX + a];
            if (!ssup[ia]) {
                float4 A = sbox[ia];
                float aa = sar[ia];
                for (int t = a + 1 + lane; t < k; t += 32) {
                    int it = slist[c * CMAX + t];
                    if (ssup[it]) continue;
                    float4 Bx = sbox[it];
                    float ix1 = fmaxf(A.x, Bx.x);
                    float iy1 = fmaxf(A.y, Bx.y);
                    float ix2 = fminf(A.z, Bx.z);
                    float iy2 = fminf(A.w, Bx.w);
                    float iw = fmaxf(ix2 - ix1, 0.f), ih = fmaxf(iy2 - iy1, 0.f);
                    float inter = iw * ih;
                    float iou = inter / (aa + sar[it] - inter + 1e-6f);
                    if (iou > IOU_THR) ssup[it] = 1;
                }
            }
            __syncwarp();
        }
    }
    __syncthreads();

    // ---- phase 9: default outputs + rank kept items + write top-100 ----
    float* ob = out;
    float* os = out + BB * 100 * 4;
    float* ol = out + BB * 100 * 5;
    for (int r = tid; r < 100; r += 1024) {
        ob[(b * 100 + r) * 4 + 0] = 0.f;
        ob[(b * 100 + r) * 4 + 1] = 0.f;
        ob[(b * 100 + r) * 4 + 2] = 0.f;
        ob[(b * 100 + r) * 4 + 3] = 0.f;
        os[b * 100 + r] = 0.f;
        ol[b * 100 + r] = -1.f;
    }
    int s0 = 2 * tid, s1 = 2 * tid + 1;
    int f0 = (s0 < KTOP) && (slab[s0] != 255) && !ssup[s0];
    int f1 = (s1 < KTOP) && (slab[s1] != 255) && !ssup[s1];
    int loc = f0 + f1;
    int inc2 = loc;
    #pragma unroll
    for (int o = 1; o < 32; o <<= 1) {
        int v = __shfl_up_sync(0xffffffffu, inc2, o);
        if (lane >= o) inc2 += v;
    }
    if (lane == 31) wtot[wid] = inc2;
    __syncthreads();
    if (wid == 0) {
        int v = wtot[lane];
        int i3 = v;
        #pragma unroll
        for (int o = 1; o < 32; o <<= 1) {
            int u3 = __shfl_up_sync(0xffffffffu, i3, o);
            if (lane >= o) i3 += u3;
        }
        wtot[lane] = i3 - v;
    }
    __syncthreads();
    int base2 = wtot[wid] + inc2 - loc;
    if (f0 && base2 < 100) {
        int r = base2;
        float off = (float)slab[s0] * offs;
        float4 bx = sbox[s0];
        ob[(b * 100 + r) * 4 + 0] = bx.x - off;
        ob[(b * 100 + r) * 4 + 1] = bx.y - off;
        ob[(b * 100 + r) * 4 + 2] = bx.z - off;
        ob[(b * 100 + r) * 4 + 3] = bx.w - off;
        os[b * 100 + r] = ssc[s0];
        ol[b * 100 + r] = (float)slab[s0];
    }
    if (f1 && base2 + f0 < 100) {
        int r = base2 + f0;
        float off = (float)slab[s1] * offs;
        float4 bx = sbox[s1];
        ob[(b * 100 + r) * 4 + 0] = bx.x - off;
        ob[(b * 100 + r) * 4 + 1] = bx.y - off;
        ob[(b * 100 + r) * 4 + 2] = bx.z - off;
        ob[(b * 100 + r) * 4 + 3] = bx.w - off;
        os[b * 100 + r] = ssc[s1];
        ol[b * 100 + r] = (float)slab[s1];
    }

    // ---- phase 10: reset counter for next graph replay (state invariant per call) ----
    __syncthreads();
    if (tid == 0) g_count[b] = 0;
}

// ---------------- launch ----------------
extern "C" void kernel_launch(void* const* d_in, const int* in_sizes, int n_in,
                              void* d_out, int out_size) {
    const float* cls   = (const float*)d_in[0];   // [B,N,81]
    const float* reg   = (const float*)d_in[1];   // [B,N,320]
    const float* props = (const float*)d_in[2];   // [B,N,4]
    const int*   hw    = (const int*)d_in[3];     // [B,2]
    float* out = (float*)d_out;

    cudaFuncSetAttribute(k_mega, cudaFuncAttributeMaxDynamicSharedMemorySize, PM_TOTAL);

    k_score<<<BB * NN / 8, 256>>>(cls);
    k_mega<<<BB, 1024, PM_TOTAL>>>(reg, props, hw, out);
}

// round 5
// speedup vs baseline: 6.7488x; 2.1389x over previous
#include <cuda_runtime.h>
#include <math.h>

#define BB 4
#define NN 2000
#define CCLS 80
#define KTOP 2000
#define CAP 8192
#define CMAX 160
#define SCORE_THR 0.05f
#define IOU_THR 0.5f
#define MAXR 4.135166556742356f   /* |log(16/1000)| */

// bucket sort params: bucket = (score_bits >> 13) - BUCKET_BASE
#define NB 5120                    /* 5 buckets per thread @ 1024 threads */
#define SCAP 4096
#define BUCKET_BASE 125542u        /* 0x3D4CCCCD >> 13  (0.05f) */

// ---------------- device scratch ----------------
__device__ unsigned long long g_keys[BB][CAP];
__device__ int g_count[BB];                    // zero at load; reset by k_sortdec
__device__ unsigned long long g_skey[BB][KTOP];
__device__ unsigned char g_slab[BB][KTOP];
__device__ float4 g_boxv[BB][KTOP];            // offset boxes, written by k_nms
__device__ unsigned char g_keep[BB][KTOP];

// ---------------- 1) softmax + threshold + compact (block-aggregated) ----------------
__global__ void k_score(const float* __restrict__ cls) {
    __shared__ unsigned long long buf[640];
    __shared__ int bcnt;
    __shared__ int gbase;
    int wib = threadIdx.x >> 5;
    int lane = threadIdx.x & 31;
    int warp = blockIdx.x * 8 + wib;
    int b = warp / NN, n = warp % NN;
    if (threadIdx.x == 0) bcnt = 0;
    __syncthreads();

    const float* p = cls + ((size_t)b * NN + n) * (CCLS + 1);
    float x0 = p[lane];
    float x1 = p[lane + 32];
    float x2 = (lane < 17) ? p[lane + 64] : -1e30f;   // idx 80 = background
    float m = fmaxf(x0, fmaxf(x1, x2));
    #pragma unroll
    for (int o = 16; o > 0; o >>= 1) m = fmaxf(m, __shfl_xor_sync(0xffffffffu, m, o));
    float e0 = expf(x0 - m);
    float e1 = expf(x1 - m);
    float e2 = (lane < 17) ? expf(x2 - m) : 0.f;
    float s = e0 + e1 + e2;
    #pragma unroll
    for (int o = 16; o > 0; o >>= 1) s += __shfl_xor_sync(0xffffffffu, s, o);

    float sc;
    sc = e0 / s;
    if (sc > SCORE_THR) {
        unsigned idx = (unsigned)(n * CCLS + lane);
        buf[atomicAdd(&bcnt, 1)] = ((unsigned long long)__float_as_uint(sc) << 32) | (0xFFFFFFFFu - idx);
    }
    sc = e1 / s;
    if (sc > SCORE_THR) {
        unsigned idx = (unsigned)(n * CCLS + lane + 32);
        buf[atomicAdd(&bcnt, 1)] = ((unsigned long long)__float_as_uint(sc) << 32) | (0xFFFFFFFFu - idx);
    }
    if (lane < 16) {
        sc = e2 / s;
        if (sc > SCORE_THR) {
            unsigned idx = (unsigned)(n * CCLS + lane + 64);
            buf[atomicAdd(&bcnt, 1)] = ((unsigned long long)__float_as_uint(sc) << 32) | (0xFFFFFFFFu - idx);
        }
    }
    __syncthreads();
    if (threadIdx.x == 0) gbase = atomicAdd(&g_count[b], bcnt);
    __syncthreads();
    int nb = bcnt, gb = gbase;
    for (int i = threadIdx.x; i < nb; i += blockDim.x) {
        int pos = gb + i;
        if (pos < CAP) g_keys[b][pos] = buf[i];
    }
}

// ---------------- 2) bucket sort per image; emit sorted keys + labels ----------------
#define SD_HIST 0                 /* int[5120] 20480 */
#define SD_SORT 20480             /* u64[4096] 32768 */
#define SD_TOTAL 53248

__global__ void k_sortdec() {
    extern __shared__ unsigned char smem[];
    int* hist = (int*)(smem + SD_HIST);
    unsigned long long* ssort = (unsigned long long*)(smem + SD_SORT);
    __shared__ int wtot[32];

    int b = blockIdx.x, tid = threadIdx.x;
    int wid = tid >> 5, lane = tid & 31;
    int cnt = min(g_count[b], CAP);

    for (int i = tid; i < NB; i += 1024) hist[i] = 0;
    for (int i = tid; i < SCAP; i += 1024) ssort[i] = 0ull;
    __syncthreads();

    for (int i = tid; i < cnt; i += 1024) {
        unsigned u = (unsigned)(g_keys[b][i] >> 32);
        int bkt = min(max((int)((u >> 13) - BUCKET_BASE), 0), NB - 1);
        atomicAdd(&hist[bkt], 1);
    }
    __syncthreads();

    // suffix exclusive scan: start[bkt] = #items in higher buckets
    int lc[5];
    int lsum = 0;
    #pragma unroll
    for (int k = 0; k < 5; k++) {
        lc[k] = hist[NB - 1 - (tid * 5 + k)];
        lsum += lc[k];
    }
    int incl = lsum;
    #pragma unroll
    for (int o = 1; o < 32; o <<= 1) {
        int v = __shfl_up_sync(0xffffffffu, incl, o);
        if (lane >= o) incl += v;
    }
    if (lane == 31) wtot[wid] = incl;
    __syncthreads();
    if (wid == 0) {
        int v = wtot[lane];
        int i2 = v;
        #pragma unroll
        for (int o = 1; o < 32; o <<= 1) {
            int u2 = __shfl_up_sync(0xffffffffu, i2, o);
            if (lane >= o) i2 += u2;
        }
        wtot[lane] = i2 - v;
    }
    __syncthreads();
    int run = wtot[wid] + incl - lsum;
    #pragma unroll
    for (int k = 0; k < 5; k++) {
        int bkt = NB - 1 - (tid * 5 + k);
        int c = lc[k];
        hist[bkt] = run;
        run += c;
    }
    __syncthreads();

    for (int i = tid; i < cnt; i += 1024) {
        unsigned long long key = g_keys[b][i];
        unsigned u = (unsigned)(key >> 32);
        int bkt = min(max((int)((u >> 13) - BUCKET_BASE), 0), NB - 1);
        int pos = atomicAdd(&hist[bkt], 1);
        if (pos < SCAP) ssort[pos] = key;
    }
    __syncthreads();

    // per-bucket insertion fix-up (full 64-bit key gives unique total order)
    for (int bkt = tid; bkt < NB; bkt += 1024) {
        int e0 = hist[bkt];
        int s0 = (bkt == NB - 1) ? 0 : hist[bkt + 1];
        if (s0 >= KTOP) continue;
        if (e0 > SCAP) e0 = SCAP;
        for (int i = s0 + 1; i < e0; i++) {
            unsigned long long v = ssort[i];
            int j = i - 1;
            while (j >= s0 && ssort[j] < v) { ssort[j + 1] = ssort[j]; j--; }
            ssort[j + 1] = v;
        }
    }
    __syncthreads();

    for (int s = tid; s < KTOP; s += 1024) {
        unsigned long long key = ssort[s];
        g_skey[b][s] = key;
        unsigned char l = 255;
        if (s < cnt && key != 0ull) {
            unsigned idx = 0xFFFFFFFFu - (unsigned)(key & 0xFFFFFFFFu);
            l = (unsigned char)(idx % CCLS);
        }
        g_slab[b][s] = l;
    }
    if (tid == 0) g_count[b] = 0;   // invariant state for next replay
}

// ---------------- 3) per-class: compact + decode + greedy NMS  (320 blocks) ----------------
__global__ void k_nms(const float* __restrict__ reg, const float* __restrict__ props,
                      const int* __restrict__ hw) {
    __shared__ unsigned char slab[2048];
    __shared__ unsigned short list[CMAX];
    __shared__ float4 bx[CMAX];
    __shared__ float ar[CMAX];
    __shared__ unsigned char sup[CMAX];
    __shared__ int wsum[8];
    __shared__ int scnt;

    int c = blockIdx.x, b = blockIdx.y;
    int tid = threadIdx.x;
    int wid = tid >> 5, lane = tid & 31;

    // coalesced label load (2000 bytes)
    {
        const uint4* src = (const uint4*)g_slab[b];
        uint4* dst = (uint4*)slab;
        if (tid < 125) dst[tid] = src[tid];
        if (tid < 48) ((unsigned char*)slab)[2000 + tid] = 255;
    }
    __syncthreads();

    // stable compaction: thread t owns s in [t*8, t*8+8)
    int f[8], pf = 0;
    #pragma unroll
    for (int i = 0; i < 8; i++) {
        int s = tid * 8 + i;
        f[i] = (s < KTOP) && (slab[s] == (unsigned char)c);
        pf += f[i];
    }
    int incl = pf;
    #pragma unroll
    for (int o = 1; o < 32; o <<= 1) {
        int v = __shfl_up_sync(0xffffffffu, incl, o);
        if (lane >= o) incl += v;
    }
    if (lane == 31) wsum[wid] = incl;
    __syncthreads();
    if (tid < 8) {
        int v = wsum[tid];
        int i2 = v;
        #pragma unroll
        for (int o = 1; o < 8; o <<= 1) {
            int u2 = __shfl_up_sync(0xffu, i2, o);
            if (tid >= o) i2 += u2;
        }
        wsum[tid] = i2 - v;
        if (tid == 7) scnt = i2;
    }
    __syncthreads();
    int r = wsum[wid] + incl - pf;
    #pragma unroll
    for (int i = 0; i < 8; i++) {
        if (f[i]) {
            int s = tid * 8 + i;
            if (r < CMAX) list[r] = (unsigned short)s;
            else g_keep[b][s] = 0;           // overflow: drop deterministically
            r++;
        }
    }
    __syncthreads();

    int k = min(scnt, CMAX);
    if (k == 0) return;

    float h = (float)hw[b * 2 + 0], w = (float)hw[b * 2 + 1];
    float offs = fmaxf(h, w) + 1.0f;
    float off = (float)c * offs;

    // decode this class's boxes (with class offset; matches reference fp rounding)
    for (int i = tid; i < k; i += 256) {
        int s = list[i];
        unsigned long long key = g_skey[b][s];
        unsigned idx = 0xFFFFFFFFu - (unsigned)(key & 0xFFFFFFFFu);
        int n = idx / CCLS;
        const float* pb = props + ((size_t)b * NN + n) * 4;
        const float* d = reg + (((size_t)b * NN + n) * CCLS + c) * 4;
        float dx = d[0] * 0.1f, dy = d[1] * 0.1f;
        float dw = fminf(fmaxf(d[2] * 0.2f, -MAXR), MAXR);
        float dh = fminf(fmaxf(d[3] * 0.2f, -MAXR), MAXR);
        float px = (pb[0] + pb[2]) * 0.5f, py = (pb[1] + pb[3]) * 0.5f;
        float pw = pb[2] - pb[0], ph = pb[3] - pb[1];
        float gx = px + pw * dx, gy = py + ph * dy;
        float gw = pw * expf(dw), gh = ph * expf(dh);
        float x1 = fminf(fmaxf(gx - gw * 0.5f, 0.f), w) + off;
        float y1 = fminf(fmaxf(gy - gh * 0.5f, 0.f), h) + off;
        float x2 = fminf(fmaxf(gx + gw * 0.5f, 0.f), w) + off;
        float y2 = fminf(fmaxf(gy + gh * 0.5f, 0.f), h) + off;
        float4 B = make_float4(x1, y1, x2, y2);
        bx[i] = B;
        ar[i] = (x2 - x1) * (y2 - y1);
        sup[i] = 0;
        g_boxv[b][s] = B;                    // k_out reads only kept items
    }
    __syncthreads();

    // greedy NMS (warp 0); list is in descending score order
    if (wid == 0) {
        for (int a = 0; a < k - 1; a++) {
            if (!sup[a]) {
                float4 A = bx[a];
                float aa = ar[a];
                for (int t = a + 1 + lane; t < k; t += 32) {
                    if (sup[t]) continue;
                    float4 Bx = bx[t];
                    float ix1 = fmaxf(A.x, Bx.x);
                    float iy1 = fmaxf(A.y, Bx.y);
                    float ix2 = fminf(A.z, Bx.z);
                    float iy2 = fminf(A.w, Bx.w);
                    float iw = fmaxf(ix2 - ix1, 0.f), ih = fmaxf(iy2 - iy1, 0.f);
                    float inter = iw * ih;
                    float iou = inter / (aa + ar[t] - inter + 1e-6f);
                    if (iou > IOU_THR) sup[t] = 1;
                }
            }
            __syncwarp();
        }
    }
    __syncthreads();

    for (int i = tid; i < k; i += 256) g_keep[b][list[i]] = 1 - sup[i];
}

// ---------------- 4) rank kept items globally, write top-100 ----------------
__global__ void k_out(const int* __restrict__ hw, float* __restrict__ out) {
    __shared__ unsigned char slab[2048];
    __shared__ unsigned char skeep[2048];
    __shared__ int wtot[32];
    int b = blockIdx.x, tid = threadIdx.x;
    int wid = tid >> 5, lane = tid & 31;

    {
        const uint4* s1 = (const uint4*)g_slab[b];
        const uint4* s2 = (const uint4*)g_keep[b];
        if (tid < 125) { ((uint4*)slab)[tid] = s1[tid]; ((uint4*)skeep)[tid] = s2[tid]; }
    }
    float h = (float)hw[b * 2 + 0], w = (float)hw[b * 2 + 1];
    float offs = fmaxf(h, w) + 1.0f;

    float* ob = out;
    float* os = out + BB * 100 * 4;
    float* ol = out + BB * 100 * 5;
    for (int r = tid; r < 100; r += 1024) {
        ob[(b * 100 + r) * 4 + 0] = 0.f;
        ob[(b * 100 + r) * 4 + 1] = 0.f;
        ob[(b * 100 + r) * 4 + 2] = 0.f;
        ob[(b * 100 + r) * 4 + 3] = 0.f;
        os[b * 100 + r] = 0.f;
        ol[b * 100 + r] = -1.f;
    }
    __syncthreads();

    int s0 = 2 * tid, s1 = 2 * tid + 1;
    int f0 = (s0 < KTOP) && (slab[s0] != 255) && skeep[s0];
    int f1 = (s1 < KTOP) && (slab[s1] != 255) && skeep[s1];
    int loc = f0 + f1;
    int incl = loc;
    #pragma unroll
    for (int o = 1; o < 32; o <<= 1) {
        int v = __shfl_up_sync(0xffffffffu, incl, o);
        if (lane >= o) incl += v;
    }
    if (lane == 31) wtot[wid] = incl;
    __syncthreads();
    if (wid == 0) {
        int v = wtot[lane];
        int i2 = v;
        #pragma unroll
        for (int o = 1; o < 32; o <<= 1) {
            int u2 = __shfl_up_sync(0xffffffffu, i2, o);
            if (lane >= o) i2 += u2;
        }
        wtot[lane] = i2 - v;
    }
    __syncthreads();
    int base = wtot[wid] + incl - loc;
    if (f0 && base < 100) {
        int r = base;
        float off = (float)slab[s0] * offs;
        float4 B = g_boxv[b][s0];
        ob[(b * 100 + r) * 4 + 0] = B.x - off;
        ob[(b * 100 + r) * 4 + 1] = B.y - off;
        ob[(b * 100 + r) * 4 + 2] = B.z - off;
        ob[(b * 100 + r) * 4 + 3] = B.w - off;
        os[b * 100 + r] = __uint_as_float((unsigned)(g_skey[b][s0] >> 32));
        ol[b * 100 + r] = (float)slab[s0];
    }
    if (f1 && base + f0 < 100) {
        int r = base + f0;
        float off = (float)slab[s1] * offs;
        float4 B = g_boxv[b][s1];
        ob[(b * 100 + r) * 4 + 0] = B.x - off;
        ob[(b * 100 + r) * 4 + 1] = B.y - off;
        ob[(b * 100 + r) * 4 + 2] = B.z - off;
        ob[(b * 100 + r) * 4 + 3] = B.w - off;
        os[b * 100 + r] = __uint_as_float((unsigned)(g_skey[b][s1] >> 32));
        ol[b * 100 + r] = (float)slab[s1];
    }
}

// ---------------- launch ----------------
extern "C" void kernel_launch(void* const* d_in, const int* in_sizes, int n_in,
                              void* d_out, int out_size) {
    const float* cls   = (const float*)d_in[0];   // [B,N,81]
    const float* reg   = (const float*)d_in[1];   // [B,N,320]
    const float* props = (const float*)d_in[2];   // [B,N,4]
    const int*   hw    = (const int*)d_in[3];     // [B,2]
    float* out = (float*)d_out;

    cudaFuncSetAttribute(k_sortdec, cudaFuncAttributeMaxDynamicSharedMemorySize, SD_TOTAL);

    k_score<<<BB * NN / 8, 256>>>(cls);
    k_sortdec<<<BB, 1024, SD_TOTAL>>>();
    k_nms<<<dim3(CCLS, BB), 256>>>(reg, props, hw);
    k_out<<<BB, 1024>>>(hw, out);
}